// round 15
// baseline (speedup 1.0000x reference)
#include <cuda_runtime.h>
#include <cooperative_groups.h>
#include <math.h>

namespace cg = cooperative_groups;

#define SB   2
#define SEQ  256
#define IND  80
#define HID  128
#define G4   512
#define F2D  256
#define NCLS 40
#define WSEG 64
#define HS   100

// ---------------- device scratch ----------------
__device__ float    d_pre [2*SEQ*SB*G4];   // [dir][s][b][512]
__device__ float    d_rnn1[SB*SEQ*F2D];
__device__ float    d_rnn2[SB*SEQ*F2D];
__device__ float    d_cum [SB*SEQ*F2D];
__device__ float    d_pd  [SB*SEQ*HS];
__device__ float    d_pe  [SB*SEQ*HS];
__device__ float    d_band[SB*SEQ*WSEG];   // band[b][i][w], j = max(0,i-64)+w

__device__ __forceinline__ float preluf(float x, float a) { return x >= 0.f ? x : a * x; }
// fast, NaN-safe gate activations (__expf: MUFU-based, ~1e-6 rel err)
__device__ __forceinline__ float fsigm(float x) { return 1.f / (1.f + __expf(-x)); }
__device__ __forceinline__ float ftanh(float x) {
    float e = __expf(-2.f * fabsf(x));
    float t = (1.f - e) / (1.f + e);
    return copysignf(t, x);
}

__device__ __forceinline__ uint32_t smem_u32(const void* p) {
    uint32_t a;
    asm("{ .reg .u64 t; cvta.to.shared.u64 t, %1; cvt.u32.u64 %0, t; }" : "=r"(a) : "l"(p));
    return a;
}
__device__ __forceinline__ void mbar_init(uint32_t bar, uint32_t cnt) {
    asm volatile("mbarrier.init.shared.b64 [%0], %1;" :: "r"(bar), "r"(cnt) : "memory");
}
// arrive on the mbarrier at the same smem offset in cluster CTA `rank` (release.cluster)
__device__ __forceinline__ void mbar_arrive_rank(uint32_t bar, uint32_t rank) {
    asm volatile(
        "{\n\t.reg .b32 r;\n\t"
        "mapa.shared::cluster.u32 r, %0, %1;\n\t"
        "mbarrier.arrive.shared::cluster.b64 _, [r];\n\t}"
        :: "r"(bar), "r"(rank) : "memory");
}
// wait for phase `parity` completion with cluster-scope acquire
__device__ __forceinline__ void mbar_wait_cluster(uint32_t bar, uint32_t parity) {
    asm volatile(
        "{\n\t.reg .pred P;\n\t"
        "LW%=:\n\t"
        "mbarrier.try_wait.parity.acquire.cluster.shared::cta.b64 P, [%0], %1, 0x989680;\n\t"
        "@P bra LD%=;\n\t"
        "bra LW%=;\n\t"
        "LD%=:\n\t}"
        :: "r"(bar), "r"(parity) : "memory");
}

// ---------------- input projection: pre = x @ Wih^T + b ----------------
// grid (S/2, 2 dirs), block 512 (one thread per gate row)
__global__ __launch_bounds__(512) void proj_kernel(
    const float* __restrict__ xin, int K, int use_r1,
    const float* __restrict__ wF, const float* __restrict__ bF,
    const float* __restrict__ wB, const float* __restrict__ bB)
{
    __shared__ float xsh[SB][2][F2D];
    const float* src = use_r1 ? d_rnn1 : xin;
    int dir = blockIdx.y;
    int s0  = blockIdx.x * 2;
    int t   = threadIdx.x;
    for (int n = t; n < SB * 2 * K; n += 512) {
        int b = n / (2 * K); int rem = n % (2 * K);
        int sl = rem / K;    int k = rem % K;
        xsh[b][sl][k] = src[(b * SEQ + s0 + sl) * K + k];
    }
    __syncthreads();
    const float* w = (dir ? wB : wF) + t * K;
    float bias = (dir ? bB : bF)[t];
    float a00 = bias, a01 = bias, a10 = bias, a11 = bias;
    const float4* w4 = (const float4*)w;
    int K4 = K >> 2;
    for (int k4 = 0; k4 < K4; k4++) {
        float4 wv = w4[k4]; int k = k4 * 4;
        a00 += wv.x*xsh[0][0][k] + wv.y*xsh[0][0][k+1] + wv.z*xsh[0][0][k+2] + wv.w*xsh[0][0][k+3];
        a01 += wv.x*xsh[0][1][k] + wv.y*xsh[0][1][k+1] + wv.z*xsh[0][1][k+2] + wv.w*xsh[0][1][k+3];
        a10 += wv.x*xsh[1][0][k] + wv.y*xsh[1][0][k+1] + wv.z*xsh[1][0][k+2] + wv.w*xsh[1][0][k+3];
        a11 += wv.x*xsh[1][1][k] + wv.y*xsh[1][1][k+1] + wv.z*xsh[1][1][k+2] + wv.w*xsh[1][1][k+3];
    }
    d_pre[((dir*SEQ + s0    ) * SB + 0) * G4 + t] = a00;
    d_pre[((dir*SEQ + s0    ) * SB + 1) * G4 + t] = a10;
    d_pre[((dir*SEQ + s0 + 1) * SB + 0) * G4 + t] = a01;
    d_pre[((dir*SEQ + s0 + 1) * SB + 1) * G4 + t] = a11;
}

// ---------------- LSTM recurrence: one 2-CTA cluster per (direction, batch) ----------------
// grid 8 = 4 clusters of 2 CTAs x 512 threads. Cluster cid: dir=cid>>1, batch=cid&1.
// CTA cr owns h indices j in [64cr, 64cr+64) (x4 gates -> 256 gate rows).
// Thread t: rl=t>>1 row-local (256 rows), half=t&1 owns 64 of 128 k's (regs).
// Per-step sync: writer warps (t<64) store h to self + 1 peer (DSMEM), elected
// lanes arrive on both CTAs' mbarriers (count=4). No cluster.sync in the loop.
__global__ __launch_bounds__(512, 1) __cluster_dims__(2, 1, 1)
void lstm_kernel(const float* __restrict__ whhF, const float* __restrict__ whhB,
                 int out_is_l2)
{
    cg::cluster_group cluster = cg::this_cluster();
    float* out = out_is_l2 ? d_rnn2 : d_rnn1;
    int blk = blockIdx.x;
    int cid = blk >> 1;
    int dir = cid >> 1, bat = cid & 1, cr = blk & 1;
    const float* whh = dir ? whhB : whhF;
    int t = threadIdx.x;
    int rl = t >> 1, half = t & 1, gate = rl >> 6, jj = rl & 63;
    int g = gate * HID + cr * 64 + jj;

    float w[64];
    const float4* wr = (const float4*)(whh + g * HID + half * 64);
#pragma unroll
    for (int q = 0; q < 16; q++) {
        float4 v = wr[q];
        w[4*q] = v.x; w[4*q+1] = v.y; w[4*q+2] = v.z; w[4*q+3] = v.w;
    }

    __shared__ float hsm[2][HID];          // double-buffered h (single batch)
    __shared__ float gsm[4][64];
    __shared__ __align__(8) unsigned long long mbar;
    uint32_t bar = smem_u32(&mbar);
    float c = 0.f;

    if (t < HID) hsm[0][t] = 0.f;          // ts=0 reads buffer 0
    if (t == 0) mbar_init(bar, 4);         // 2 elected lanes x 2 CTAs

    float* peer[2];
#pragma unroll
    for (int r = 0; r < 2; r++) peer[r] = cluster.map_shared_rank(&hsm[0][0], r);

    cluster.sync();                        // init + mbarriers visible; peers resident

    const float* preb = d_pre + (dir * SEQ) * (SB * G4) + bat * G4 + g;
    float preC = preb[(dir ? (SEQ - 1) : 0) * (SB * G4)];   // prefetched pre for ts=0

    for (int ts = 0; ts < SEQ; ts++) {
        int rb = ts & 1, wb = rb ^ 1;
        // prefetch next step's pre (independent of recurrence -> fully hidden)
        int snext = dir ? (SEQ - 2 - ts) : (ts + 1);
        float preN = (ts < SEQ - 1) ? preb[snext * (SB * G4)] : 0.f;

        const float4* h4 = (const float4*)&hsm[rb][half * 64];
        float a0 = 0.f, a1 = 0.f, a2 = 0.f, a3 = 0.f;   // 4-way RAW chain split
#pragma unroll
        for (int q = 0; q < 16; q += 4) {
            float4 v0 = h4[q], v1 = h4[q+1], v2 = h4[q+2], v3 = h4[q+3];
            a0 += w[4*q   ]*v0.x + w[4*q+1 ]*v0.y + w[4*q+2 ]*v0.z + w[4*q+3 ]*v0.w;
            a1 += w[4*q+4 ]*v1.x + w[4*q+5 ]*v1.y + w[4*q+6 ]*v1.z + w[4*q+7 ]*v1.w;
            a2 += w[4*q+8 ]*v2.x + w[4*q+9 ]*v2.y + w[4*q+10]*v2.z + w[4*q+11]*v2.w;
            a3 += w[4*q+12]*v3.x + w[4*q+13]*v3.y + w[4*q+14]*v3.z + w[4*q+15]*v3.w;
        }
        float a = (a0 + a1) + (a2 + a3);
        a += __shfl_xor_sync(0xffffffffu, a, 1);
        if (half == 0) gsm[gate][jj] = preC + a;
        // after this barrier: every local warp done reading hsm[rb] and gsm
        __syncthreads();
        if (t < 64) {
            float gi = gsm[0][t], gf = gsm[1][t];
            float gg = gsm[2][t], go = gsm[3][t];
            c = fsigm(gf) * c + fsigm(gi) * ftanh(gg);
            float h = fsigm(go) * ftanh(c);
            int cj = cr * 64 + t;
            int off = wb * HID + cj;
            peer[0][off] = h;                               // DSMEM broadcast (2 ranks)
            peer[1][off] = h;
            int s = dir ? (SEQ - 1 - ts) : ts;
            out[(bat * SEQ + s) * F2D + dir * HID + cj] = h;
            __syncwarp();                                   // stores before elected arrive
            if ((t & 31) == 0) {                            // lane 0 of warps 0,1
                mbar_arrive_rank(bar, 0u);
                mbar_arrive_rank(bar, 1u);
            }
        }
        mbar_wait_cluster(bar, (uint32_t)(ts & 1));
        preC = preN;
    }
}

// ---------------- inclusive cumsum over s ----------------
__global__ void cumsum_kernel() {
    int b = blockIdx.x, k = threadIdx.x;
    float acc = 0.f;
#pragma unroll 8
    for (int s = 0; s < SEQ; s++) {
        acc += d_rnn2[(b * SEQ + s) * F2D + k];
        d_cum[(b * SEQ + s) * F2D + k] = acc;
    }
}

// ---------------- per-position d/e parts of score MLP layer 1 ----------------
__global__ __launch_bounds__(128) void pdpe_kernel(
    const float* __restrict__ w1, const float* __restrict__ b1,
    const float* __restrict__ a0p)
{
    int b = blockIdx.x >> 8, s = blockIdx.x & 255, t = threadIdx.x;
    float a0 = *a0p;
    __shared__ float px[F2D];
    for (int k = t; k < F2D; k += 128) px[k] = preluf(d_rnn2[(b * SEQ + s) * F2D + k], a0);
    __syncthreads();
    if (t < HS) {
        const float4* wd = (const float4*)(w1 + t * 768 + 256);
        const float4* we = (const float4*)(w1 + t * 768 + 512);
        float ad = 0.f, ae = 0.f;
        for (int k4 = 0; k4 < 64; k4++) {
            float4 v = wd[k4], u = we[k4]; int k = k4 * 4;
            ad += v.x*px[k] + v.y*px[k+1] + v.z*px[k+2] + v.w*px[k+3];
            ae += u.x*px[k] + u.y*px[k+1] + u.z*px[k+2] + u.w*px[k+3];
        }
        d_pd[(b * SEQ + s) * HS + t] = ad;
        d_pe[(b * SEQ + s) * HS + t] = ae + b1[t];
    }
}

// ---------------- cls + bin MLPs ----------------
__global__ __launch_bounds__(160) void clsbin_kernel(
    const float* a_c0, const float* w_c1, const float* b_c1,
    const float* a_c1, const float* w_c2, const float* b_c2,
    const float* a_b0, const float* w_b1, const float* b_b1,
    const float* a_b1, const float* w_b2, const float* b_b2,
    float* __restrict__ out)
{
    int b = blockIdx.x >> 8, s = blockIdx.x & 255, t = threadIdx.x;
    __shared__ float xr[F2D];
    __shared__ float hc[80], hb[80];
    for (int k = t; k < F2D; k += 160) xr[k] = d_rnn2[(b * SEQ + s) * F2D + k];
    __syncthreads();
    {
        int row = t % 80;
        bool isb = t >= 80;
        const float4* wrow = (const float4*)((isb ? w_b1 : w_c1) + row * F2D);
        float alpha = isb ? *a_b0 : *a_c0;
        float acc = (isb ? b_b1 : b_c1)[row];
        for (int k4 = 0; k4 < 64; k4++) {
            float4 wv = wrow[k4]; int k = k4 * 4;
            acc += wv.x * preluf(xr[k],   alpha) + wv.y * preluf(xr[k+1], alpha)
                 + wv.z * preluf(xr[k+2], alpha) + wv.w * preluf(xr[k+3], alpha);
        }
        if (isb) hb[row] = acc; else hc[row] = acc;
    }
    __syncthreads();
    if (t < NCLS) {
        float a1 = *a_c1, acc = b_c2[t];
        for (int q = 0; q < 80; q++) acc += w_c2[t * 80 + q] * preluf(hc[q], a1);
        out[(b * SEQ + s) * NCLS + t] = acc;
    } else if (t < NCLS + 2) {
        int r = t - NCLS;
        float a1 = *a_b1, acc = b_b2[r];
        for (int q = 0; q < 80; q++) acc += w_b2[r * 80 + q] * preluf(hb[q], a1);
        out[SB*SEQ*NCLS + (b * SEQ + s) * 2 + r] = acc;
    }
}

// ---------------- banded pairwise scores ----------------
// grid 510: b = bid&1, i = 1 + (bid>>1). smem: phi(64 x 256 padded) + W1c(112 x 256 padded)
#define RPAD 65   // float4 row stride (260 floats) -> 2-way bank conflicts only
__global__ __launch_bounds__(256) void band_kernel(
    const float* __restrict__ w1, const float* __restrict__ w2,
    const float* __restrict__ b2, const float* __restrict__ a0p,
    const float* __restrict__ a1p)
{
    extern __shared__ float smraw[];
    float4* phi = (float4*)smraw;
    float4* w1s = phi + 64 * RPAD;
    int b = blockIdx.x & 1;
    int i = 1 + (blockIdx.x >> 1);
    int start = i > WSEG ? i - WSEG : 0;
    int t = threadIdx.x;
    float a0 = *a0p;

    for (int n = t; n < 112 * 64; n += 256) {           // stage W1 cols [0,256)
        int r = n >> 6, k4 = n & 63;
        float4 v = make_float4(0.f, 0.f, 0.f, 0.f);
        if (r < HS) v = ((const float4*)(w1 + r * 768))[k4];
        w1s[r * RPAD + k4] = v;
    }
    const float4* cum4 = (const float4*)d_cum;
    for (int n = t; n < 64 * 64; n += 256) {            // phi = prelu(cum_i - cum_j)
        int wdx = n >> 6, k4 = n & 63;
        int j = start + wdx;
        float4 ci = cum4[(b * SEQ + i) * 64 + k4];
        float4 cj = cum4[(b * SEQ + j) * 64 + k4];
        float4 d;
        d.x = preluf(ci.x - cj.x, a0); d.y = preluf(ci.y - cj.y, a0);
        d.z = preluf(ci.z - cj.z, a0); d.w = preluf(ci.w - cj.w, a0);
        phi[wdx * RPAD + k4] = d;
    }
    __syncthreads();

    int tw = t & 15, tr = t >> 4;
    float acc[4][7];
#pragma unroll
    for (int q = 0; q < 4; q++)
#pragma unroll
        for (int p = 0; p < 7; p++) acc[q][p] = 0.f;

    for (int k4 = 0; k4 < 64; k4++) {
        float4 ph[4];
#pragma unroll
        for (int q = 0; q < 4; q++) ph[q] = phi[(tr + 16 * q) * RPAD + k4];
#pragma unroll
        for (int p = 0; p < 7; p++) {
            float4 wv = w1s[(tw + 16 * p) * RPAD + k4];
#pragma unroll
            for (int q = 0; q < 4; q++)
                acc[q][p] += ph[q].x*wv.x + ph[q].y*wv.y + ph[q].z*wv.z + ph[q].w*wv.w;
        }
    }

    float a1 = *a1p;
    float loc[4] = {0.f, 0.f, 0.f, 0.f};
#pragma unroll
    for (int p = 0; p < 7; p++) {
        int r = tw + 16 * p;
        float w2v = (r < HS) ? w2[r] : 0.f;
        float pev = (r < HS) ? d_pe[(b * SEQ + i) * HS + r] : 0.f;
#pragma unroll
        for (int q = 0; q < 4; q++) {
            int j = start + tr + 16 * q;
            float pdv = (r < HS) ? d_pd[(b * SEQ + j) * HS + r] : 0.f;
            float h = acc[q][p] + pdv + pev;
            loc[q] += preluf(h, a1) * w2v;
        }
    }
#pragma unroll
    for (int off = 8; off >= 1; off >>= 1)
#pragma unroll
        for (int q = 0; q < 4; q++)
            loc[q] += __shfl_xor_sync(0xffffffffu, loc[q], off, 16);
    if (tw == 0) {
        float bb = b2[0];
#pragma unroll
        for (int q = 0; q < 4; q++)
            d_band[(b * SEQ + i) * WSEG + tr + 16 * q] = loc[q] + bb;
    }
}

// ---------------- DP + backtrack (single CTA, band in smem) ----------------
__global__ __launch_bounds__(256) void dp_kernel(const int* __restrict__ lengths,
                                                 float* __restrict__ out)
{
    extern __shared__ float bs[];               // 2*256*64 floats
    __shared__ float best[SB][SEQ];
    __shared__ int   bp[SB][SEQ];
    int t = threadIdx.x;
    const float4* src = (const float4*)d_band;
    float4* dst = (float4*)bs;
    for (int n = t; n < SB * SEQ * WSEG / 4; n += 256) dst[n] = src[n];
    float* bm = out + SB*SEQ*NCLS + SB*SEQ*2;
    for (int n = t; n < SB * SEQ; n += 256) bm[n] = 0.f;
    if (t < SB) { best[t][0] = 0.f; bp[t][0] = 0; }
    __syncthreads();

    if (t < 64) {
        int b = t >> 5, l = t & 31;
        for (int i = 1; i < SEQ; i++) {
            int start = i > WSEG ? i - WSEG : 0;
            const float* row = &bs[(b * SEQ + i) * WSEG];
            int j1 = start + l;
            float v1 = (j1 < i) ? best[b][j1] + row[l] : -1e9f;
            int j2 = start + l + 32;
            float v2 = (j2 < i) ? best[b][j2] + row[l + 32] : -1e9f;
            float v; int wj;
            if (v2 > v1) { v = v2; wj = j2; } else { v = v1; wj = j1; }
#pragma unroll
            for (int off = 16; off >= 1; off >>= 1) {
                float ov = __shfl_xor_sync(0xffffffffu, v, off);
                int   oj = __shfl_xor_sync(0xffffffffu, wj, off);
                if (ov > v || (ov == v && oj < wj)) { v = ov; wj = oj; }
            }
            if (l == 0) { best[b][i] = v; bp[b][i] = wj; }
            __syncwarp();
        }
    }
    __syncthreads();
    if (t == 0 || t == 32) {
        int b = t >> 5;
        int cur = lengths[b] - 1;
        float acc = 0.f;
        while (true) {
            bm[b * SEQ + cur] = 1.f;
            if (cur == 0) break;
            int prev = bp[b][cur];
            int start = cur > WSEG ? cur - WSEG : 0;
            acc += bs[(b * SEQ + cur) * WSEG + (prev - start)];
            cur = prev;
        }
        out[SB*SEQ*NCLS + SB*SEQ*2 + SB*SEQ + b] = acc;
    }
}

// ---------------- launch ----------------
extern "C" void kernel_launch(void* const* d_in, const int* in_sizes, int n_in,
                              void* d_out, int out_size)
{
    const float* x      = (const float*)d_in[0];
    const int*   lens   = (const int*)  d_in[1];
    const float* wih0f  = (const float*)d_in[2];
    const float* whh0f  = (const float*)d_in[3];
    const float* b0f    = (const float*)d_in[4];
    const float* wih0b  = (const float*)d_in[5];
    const float* whh0b  = (const float*)d_in[6];
    const float* b0b    = (const float*)d_in[7];
    const float* wih1f  = (const float*)d_in[8];
    const float* whh1f  = (const float*)d_in[9];
    const float* b1f    = (const float*)d_in[10];
    const float* wih1b  = (const float*)d_in[11];
    const float* whh1b  = (const float*)d_in[12];
    const float* b1b    = (const float*)d_in[13];
    const float* a_s0   = (const float*)d_in[14];
    const float* w_s1   = (const float*)d_in[15];
    const float* b_s1   = (const float*)d_in[16];
    const float* a_s1   = (const float*)d_in[17];
    const float* w_s2   = (const float*)d_in[18];
    const float* b_s2   = (const float*)d_in[19];
    const float* a_c0   = (const float*)d_in[20];
    const float* w_c1   = (const float*)d_in[21];
    const float* b_c1   = (const float*)d_in[22];
    const float* a_c1   = (const float*)d_in[23];
    const float* w_c2   = (const float*)d_in[24];
    const float* b_c2   = (const float*)d_in[25];
    const float* a_b0   = (const float*)d_in[26];
    const float* w_b1   = (const float*)d_in[27];
    const float* b_b1   = (const float*)d_in[28];
    const float* a_b1   = (const float*)d_in[29];
    const float* w_b2   = (const float*)d_in[30];
    const float* b_b2   = (const float*)d_in[31];
    float* out = (float*)d_out;

    cudaFuncSetAttribute(band_kernel, cudaFuncAttributeMaxDynamicSharedMemorySize, 183040);
    cudaFuncSetAttribute(dp_kernel,   cudaFuncAttributeMaxDynamicSharedMemorySize, 131072);

    proj_kernel<<<dim3(128, 2), 512>>>(x, IND, 0, wih0f, b0f, wih0b, b0b);
    lstm_kernel<<<8, 512>>>(whh0f, whh0b, 0);
    proj_kernel<<<dim3(128, 2), 512>>>(x, F2D, 1, wih1f, b1f, wih1b, b1b);
    lstm_kernel<<<8, 512>>>(whh1f, whh1b, 1);
    cumsum_kernel<<<2, 256>>>();
    pdpe_kernel<<<512, 128>>>(w_s1, b_s1, a_s0);
    clsbin_kernel<<<512, 160>>>(a_c0, w_c1, b_c1, a_c1, w_c2, b_c2,
                                a_b0, w_b1, b_b1, a_b1, w_b2, b_b2, out);
    band_kernel<<<510, 256, 183040>>>(w_s1, w_s2, b_s2, a_s0, a_s1);
    dp_kernel<<<1, 256, 131072>>>(lens, out);
}

// round 17
// speedup vs baseline: 1.1326x; 1.1326x over previous
#include <cuda_runtime.h>
#include <cooperative_groups.h>
#include <math.h>

namespace cg = cooperative_groups;

#define SB   2
#define SEQ  256
#define IND  80
#define HID  128
#define G4   512
#define F2D  256
#define NCLS 40
#define WSEG 64
#define HS   100

// ---------------- device scratch ----------------
__device__ float    d_pre [2*SEQ*SB*G4];   // [dir][s][b][512]
__device__ float    d_rnn1[SB*SEQ*F2D];
__device__ float    d_rnn2[SB*SEQ*F2D];
__device__ float    d_cum [SB*SEQ*F2D];
__device__ float    d_pd  [SB*SEQ*HS];
__device__ float    d_pe  [SB*SEQ*HS];
__device__ float    d_band[SB*SEQ*WSEG];   // band[b][i][w], j = max(0,i-64)+w

__device__ __forceinline__ float preluf(float x, float a) { return x >= 0.f ? x : a * x; }
// fast, NaN-safe gate activations (__expf: MUFU-based, ~1e-6 rel err)
__device__ __forceinline__ float fsigm(float x) { return 1.f / (1.f + __expf(-x)); }
__device__ __forceinline__ float ftanh(float x) {
    float e = __expf(-2.f * fabsf(x));
    float t = (1.f - e) / (1.f + e);
    return copysignf(t, x);
}

__device__ __forceinline__ uint32_t smem_u32(const void* p) {
    uint32_t a;
    asm("{ .reg .u64 t; cvta.to.shared.u64 t, %1; cvt.u32.u64 %0, t; }" : "=r"(a) : "l"(p));
    return a;
}
__device__ __forceinline__ void mbar_init(uint32_t bar, uint32_t cnt) {
    asm volatile("mbarrier.init.shared.b64 [%0], %1;" :: "r"(bar), "r"(cnt) : "memory");
}
// arrive on the mbarrier at the same smem offset in cluster CTA `rank` (release.cluster)
__device__ __forceinline__ void mbar_arrive_rank(uint32_t bar, uint32_t rank) {
    asm volatile(
        "{\n\t.reg .b32 r;\n\t"
        "mapa.shared::cluster.u32 r, %0, %1;\n\t"
        "mbarrier.arrive.shared::cluster.b64 _, [r];\n\t}"
        :: "r"(bar), "r"(rank) : "memory");
}
// wait for phase `parity` completion with cluster-scope acquire
__device__ __forceinline__ void mbar_wait_cluster(uint32_t bar, uint32_t parity) {
    asm volatile(
        "{\n\t.reg .pred P;\n\t"
        "LW%=:\n\t"
        "mbarrier.try_wait.parity.acquire.cluster.shared::cta.b64 P, [%0], %1, 0x989680;\n\t"
        "@P bra LD%=;\n\t"
        "bra LW%=;\n\t"
        "LD%=:\n\t}"
        :: "r"(bar), "r"(parity) : "memory");
}

// ---------------- input projection: pre = x @ Wih^T + b ----------------
// grid (S/2, 2 dirs), block 512 (one thread per gate row)
__global__ __launch_bounds__(512) void proj_kernel(
    const float* __restrict__ xin, int K, int use_r1,
    const float* __restrict__ wF, const float* __restrict__ bF,
    const float* __restrict__ wB, const float* __restrict__ bB)
{
    __shared__ float xsh[SB][2][F2D];
    const float* src = use_r1 ? d_rnn1 : xin;
    int dir = blockIdx.y;
    int s0  = blockIdx.x * 2;
    int t   = threadIdx.x;
    for (int n = t; n < SB * 2 * K; n += 512) {
        int b = n / (2 * K); int rem = n % (2 * K);
        int sl = rem / K;    int k = rem % K;
        xsh[b][sl][k] = src[(b * SEQ + s0 + sl) * K + k];
    }
    __syncthreads();
    const float* w = (dir ? wB : wF) + t * K;
    float bias = (dir ? bB : bF)[t];
    float a00 = bias, a01 = bias, a10 = bias, a11 = bias;
    const float4* w4 = (const float4*)w;
    int K4 = K >> 2;
    for (int k4 = 0; k4 < K4; k4++) {
        float4 wv = w4[k4]; int k = k4 * 4;
        a00 += wv.x*xsh[0][0][k] + wv.y*xsh[0][0][k+1] + wv.z*xsh[0][0][k+2] + wv.w*xsh[0][0][k+3];
        a01 += wv.x*xsh[0][1][k] + wv.y*xsh[0][1][k+1] + wv.z*xsh[0][1][k+2] + wv.w*xsh[0][1][k+3];
        a10 += wv.x*xsh[1][0][k] + wv.y*xsh[1][0][k+1] + wv.z*xsh[1][0][k+2] + wv.w*xsh[1][0][k+3];
        a11 += wv.x*xsh[1][1][k] + wv.y*xsh[1][1][k+1] + wv.z*xsh[1][1][k+2] + wv.w*xsh[1][1][k+3];
    }
    d_pre[((dir*SEQ + s0    ) * SB + 0) * G4 + t] = a00;
    d_pre[((dir*SEQ + s0    ) * SB + 1) * G4 + t] = a10;
    d_pre[((dir*SEQ + s0 + 1) * SB + 0) * G4 + t] = a01;
    d_pre[((dir*SEQ + s0 + 1) * SB + 1) * G4 + t] = a11;
}

// ---------------- LSTM recurrence: one 4-CTA cluster per (direction, batch) ----------------
// grid 16 = 4 clusters of 4 CTAs x 256 threads. Cluster cid: dir=cid>>1, batch=cid&1.
// CTA cr owns h indices j in [32cr, 32cr+32) (x4 gates -> 128 gate rows).
// GEMV: thread t: rl=t>>1 row-local, half=t&1 owns 64 of 128 k's (weights in regs),
//       4-way split accumulators; next-step pre prefetched.
// Writer: warps 0-3 ALL redundantly compute the (identical) gate chain for the
//         CTA's 32 cells; warp w stores h to rank w only and arrives at rank w's
//         mbarrier (count=4). The mbar_wait proves the h exchange; the trailing
//         __syncthreads proves LOCAL writer warps finished reading gsm before
//         the next step's GEMV overwrites it (the round-16 race).
__global__ __launch_bounds__(256, 1) __cluster_dims__(4, 1, 1)
void lstm_kernel(const float* __restrict__ whhF, const float* __restrict__ whhB,
                 int out_is_l2)
{
    cg::cluster_group cluster = cg::this_cluster();
    float* out = out_is_l2 ? d_rnn2 : d_rnn1;
    int blk = blockIdx.x;
    int cid = blk >> 2;
    int dir = cid >> 1, bat = cid & 1, cr = blk & 3;
    const float* whh = dir ? whhB : whhF;
    int t = threadIdx.x;
    int rl = t >> 1, half = t & 1, gate = rl >> 5, jj = rl & 31;
    int g = gate * HID + cr * 32 + jj;

    float w[64];
    const float4* wr = (const float4*)(whh + g * HID + half * 64);
#pragma unroll
    for (int q = 0; q < 16; q++) {
        float4 v = wr[q];
        w[4*q] = v.x; w[4*q+1] = v.y; w[4*q+2] = v.z; w[4*q+3] = v.w;
    }

    __shared__ float hsm[2][HID];          // double-buffered h (single batch)
    __shared__ float gsm[4][32];
    __shared__ __align__(8) unsigned long long mbar;
    uint32_t bar = smem_u32(&mbar);
    float c = 0.f;                          // replicated in warps 0-3 (identical)

    if (t < HID) hsm[0][t] = 0.f;          // ts=0 reads buffer 0
    if (t == 0) mbar_init(bar, 4);         // 1 arrive per CTA per rank

    float* peer[4];
#pragma unroll
    for (int r = 0; r < 4; r++) peer[r] = cluster.map_shared_rank(&hsm[0][0], r);

    cluster.sync();                        // init + mbarriers visible; peers resident

    const float* preb = d_pre + (dir * SEQ) * (SB * G4) + bat * G4 + g;
    float preC = preb[(dir ? (SEQ - 1) : 0) * (SB * G4)];   // prefetched pre for ts=0

    int wwarp = t >> 5;                    // writer warp id (0..7), writers are 0-3
    int wlane = t & 31;

    for (int ts = 0; ts < SEQ; ts++) {
        int rb = ts & 1, wb = rb ^ 1;
        // prefetch next step's pre (independent of recurrence -> fully hidden)
        int snext = dir ? (SEQ - 2 - ts) : (ts + 1);
        float preN = (ts < SEQ - 1) ? preb[snext * (SB * G4)] : 0.f;

        const float4* h4 = (const float4*)&hsm[rb][half * 64];
        float a0 = 0.f, a1 = 0.f, a2 = 0.f, a3 = 0.f;   // 4-way RAW chain split
#pragma unroll
        for (int q = 0; q < 16; q += 4) {
            float4 v0 = h4[q], v1 = h4[q+1], v2 = h4[q+2], v3 = h4[q+3];
            a0 += w[4*q   ]*v0.x + w[4*q+1 ]*v0.y + w[4*q+2 ]*v0.z + w[4*q+3 ]*v0.w;
            a1 += w[4*q+4 ]*v1.x + w[4*q+5 ]*v1.y + w[4*q+6 ]*v1.z + w[4*q+7 ]*v1.w;
            a2 += w[4*q+8 ]*v2.x + w[4*q+9 ]*v2.y + w[4*q+10]*v2.z + w[4*q+11]*v2.w;
            a3 += w[4*q+12]*v3.x + w[4*q+13]*v3.y + w[4*q+14]*v3.z + w[4*q+15]*v3.w;
        }
        float a = (a0 + a1) + (a2 + a3);
        a += __shfl_xor_sync(0xffffffffu, a, 1);
        if (half == 0) gsm[gate][jj] = preC + a;
        // after this barrier: every local warp done reading hsm[rb]; gsm complete
        __syncthreads();
        if (t < 128) {
            // all 4 writer warps compute identical gates (deterministic fp)
            float gi = gsm[0][wlane], gf = gsm[1][wlane];
            float gg = gsm[2][wlane], go = gsm[3][wlane];
            c = fsigm(gf) * c + fsigm(gi) * ftanh(gg);
            float h = fsigm(go) * ftanh(c);
            int cj = cr * 32 + wlane;
            int off = wb * HID + cj;
            peer[wwarp][off] = h;                           // warp w -> rank w only
            if (wwarp == 0) {
                int s = dir ? (SEQ - 1 - ts) : ts;
                out[(bat * SEQ + s) * F2D + dir * HID + cj] = h;
            }
            __syncwarp();                                   // store before elected arrive
            if (wlane == 0) mbar_arrive_rank(bar, (uint32_t)wwarp);
        }
        mbar_wait_cluster(bar, (uint32_t)(ts & 1));
        // local ordering: writer warps must finish reading gsm before the next
        // step's GEMV (half==0 lanes) overwrites it. This was the r16 race.
        __syncthreads();
        preC = preN;
    }
}

// ---------------- inclusive cumsum over s ----------------
__global__ void cumsum_kernel() {
    int b = blockIdx.x, k = threadIdx.x;
    float acc = 0.f;
#pragma unroll 8
    for (int s = 0; s < SEQ; s++) {
        acc += d_rnn2[(b * SEQ + s) * F2D + k];
        d_cum[(b * SEQ + s) * F2D + k] = acc;
    }
}

// ---------------- per-position d/e parts of score MLP layer 1 ----------------
__global__ __launch_bounds__(128) void pdpe_kernel(
    const float* __restrict__ w1, const float* __restrict__ b1,
    const float* __restrict__ a0p)
{
    int b = blockIdx.x >> 8, s = blockIdx.x & 255, t = threadIdx.x;
    float a0 = *a0p;
    __shared__ float px[F2D];
    for (int k = t; k < F2D; k += 128) px[k] = preluf(d_rnn2[(b * SEQ + s) * F2D + k], a0);
    __syncthreads();
    if (t < HS) {
        const float4* wd = (const float4*)(w1 + t * 768 + 256);
        const float4* we = (const float4*)(w1 + t * 768 + 512);
        float ad = 0.f, ae = 0.f;
        for (int k4 = 0; k4 < 64; k4++) {
            float4 v = wd[k4], u = we[k4]; int k = k4 * 4;
            ad += v.x*px[k] + v.y*px[k+1] + v.z*px[k+2] + v.w*px[k+3];
            ae += u.x*px[k] + u.y*px[k+1] + u.z*px[k+2] + u.w*px[k+3];
        }
        d_pd[(b * SEQ + s) * HS + t] = ad;
        d_pe[(b * SEQ + s) * HS + t] = ae + b1[t];
    }
}

// ---------------- cls + bin MLPs ----------------
__global__ __launch_bounds__(160) void clsbin_kernel(
    const float* a_c0, const float* w_c1, const float* b_c1,
    const float* a_c1, const float* w_c2, const float* b_c2,
    const float* a_b0, const float* w_b1, const float* b_b1,
    const float* a_b1, const float* w_b2, const float* b_b2,
    float* __restrict__ out)
{
    int b = blockIdx.x >> 8, s = blockIdx.x & 255, t = threadIdx.x;
    __shared__ float xr[F2D];
    __shared__ float hc[80], hb[80];
    for (int k = t; k < F2D; k += 160) xr[k] = d_rnn2[(b * SEQ + s) * F2D + k];
    __syncthreads();
    {
        int row = t % 80;
        bool isb = t >= 80;
        const float4* wrow = (const float4*)((isb ? w_b1 : w_c1) + row * F2D);
        float alpha = isb ? *a_b0 : *a_c0;
        float acc = (isb ? b_b1 : b_c1)[row];
        for (int k4 = 0; k4 < 64; k4++) {
            float4 wv = wrow[k4]; int k = k4 * 4;
            acc += wv.x * preluf(xr[k],   alpha) + wv.y * preluf(xr[k+1], alpha)
                 + wv.z * preluf(xr[k+2], alpha) + wv.w * preluf(xr[k+3], alpha);
        }
        if (isb) hb[row] = acc; else hc[row] = acc;
    }
    __syncthreads();
    if (t < NCLS) {
        float a1 = *a_c1, acc = b_c2[t];
        for (int q = 0; q < 80; q++) acc += w_c2[t * 80 + q] * preluf(hc[q], a1);
        out[(b * SEQ + s) * NCLS + t] = acc;
    } else if (t < NCLS + 2) {
        int r = t - NCLS;
        float a1 = *a_b1, acc = b_b2[r];
        for (int q = 0; q < 80; q++) acc += w_b2[r * 80 + q] * preluf(hb[q], a1);
        out[SB*SEQ*NCLS + (b * SEQ + s) * 2 + r] = acc;
    }
}

// ---------------- banded pairwise scores ----------------
// grid 510: b = bid&1, i = 1 + (bid>>1). smem: phi(64 x 256 padded) + W1c(112 x 256 padded)
#define RPAD 65   // float4 row stride (260 floats) -> 2-way bank conflicts only
__global__ __launch_bounds__(256) void band_kernel(
    const float* __restrict__ w1, const float* __restrict__ w2,
    const float* __restrict__ b2, const float* __restrict__ a0p,
    const float* __restrict__ a1p)
{
    extern __shared__ float smraw[];
    float4* phi = (float4*)smraw;
    float4* w1s = phi + 64 * RPAD;
    int b = blockIdx.x & 1;
    int i = 1 + (blockIdx.x >> 1);
    int start = i > WSEG ? i - WSEG : 0;
    int t = threadIdx.x;
    float a0 = *a0p;

    for (int n = t; n < 112 * 64; n += 256) {           // stage W1 cols [0,256)
        int r = n >> 6, k4 = n & 63;
        float4 v = make_float4(0.f, 0.f, 0.f, 0.f);
        if (r < HS) v = ((const float4*)(w1 + r * 768))[k4];
        w1s[r * RPAD + k4] = v;
    }
    const float4* cum4 = (const float4*)d_cum;
    for (int n = t; n < 64 * 64; n += 256) {            // phi = prelu(cum_i - cum_j)
        int wdx = n >> 6, k4 = n & 63;
        int j = start + wdx;
        float4 ci = cum4[(b * SEQ + i) * 64 + k4];
        float4 cj = cum4[(b * SEQ + j) * 64 + k4];
        float4 d;
        d.x = preluf(ci.x - cj.x, a0); d.y = preluf(ci.y - cj.y, a0);
        d.z = preluf(ci.z - cj.z, a0); d.w = preluf(ci.w - cj.w, a0);
        phi[wdx * RPAD + k4] = d;
    }
    __syncthreads();

    int tw = t & 15, tr = t >> 4;
    float acc[4][7];
#pragma unroll
    for (int q = 0; q < 4; q++)
#pragma unroll
        for (int p = 0; p < 7; p++) acc[q][p] = 0.f;

    for (int k4 = 0; k4 < 64; k4++) {
        float4 ph[4];
#pragma unroll
        for (int q = 0; q < 4; q++) ph[q] = phi[(tr + 16 * q) * RPAD + k4];
#pragma unroll
        for (int p = 0; p < 7; p++) {
            float4 wv = w1s[(tw + 16 * p) * RPAD + k4];
#pragma unroll
            for (int q = 0; q < 4; q++)
                acc[q][p] += ph[q].x*wv.x + ph[q].y*wv.y + ph[q].z*wv.z + ph[q].w*wv.w;
        }
    }

    float a1 = *a1p;
    float loc[4] = {0.f, 0.f, 0.f, 0.f};
#pragma unroll
    for (int p = 0; p < 7; p++) {
        int r = tw + 16 * p;
        float w2v = (r < HS) ? w2[r] : 0.f;
        float pev = (r < HS) ? d_pe[(b * SEQ + i) * HS + r] : 0.f;
#pragma unroll
        for (int q = 0; q < 4; q++) {
            int j = start + tr + 16 * q;
            float pdv = (r < HS) ? d_pd[(b * SEQ + j) * HS + r] : 0.f;
            float h = acc[q][p] + pdv + pev;
            loc[q] += preluf(h, a1) * w2v;
        }
    }
#pragma unroll
    for (int off = 8; off >= 1; off >>= 1)
#pragma unroll
        for (int q = 0; q < 4; q++)
            loc[q] += __shfl_xor_sync(0xffffffffu, loc[q], off, 16);
    if (tw == 0) {
        float bb = b2[0];
#pragma unroll
        for (int q = 0; q < 4; q++)
            d_band[(b * SEQ + i) * WSEG + tr + 16 * q] = loc[q] + bb;
    }
}

// ---------------- DP + backtrack (single CTA, band in smem) ----------------
__global__ __launch_bounds__(256) void dp_kernel(const int* __restrict__ lengths,
                                                 float* __restrict__ out)
{
    extern __shared__ float bs[];               // 2*256*64 floats
    __shared__ float best[SB][SEQ];
    __shared__ int   bp[SB][SEQ];
    int t = threadIdx.x;
    const float4* src = (const float4*)d_band;
    float4* dst = (float4*)bs;
    for (int n = t; n < SB * SEQ * WSEG / 4; n += 256) dst[n] = src[n];
    float* bm = out + SB*SEQ*NCLS + SB*SEQ*2;
    for (int n = t; n < SB * SEQ; n += 256) bm[n] = 0.f;
    if (t < SB) { best[t][0] = 0.f; bp[t][0] = 0; }
    __syncthreads();

    if (t < 64) {
        int b = t >> 5, l = t & 31;
        for (int i = 1; i < SEQ; i++) {
            int start = i > WSEG ? i - WSEG : 0;
            const float* row = &bs[(b * SEQ + i) * WSEG];
            int j1 = start + l;
            float v1 = (j1 < i) ? best[b][j1] + row[l] : -1e9f;
            int j2 = start + l + 32;
            float v2 = (j2 < i) ? best[b][j2] + row[l + 32] : -1e9f;
            float v; int wj;
            if (v2 > v1) { v = v2; wj = j2; } else { v = v1; wj = j1; }
#pragma unroll
            for (int off = 16; off >= 1; off >>= 1) {
                float ov = __shfl_xor_sync(0xffffffffu, v, off);
                int   oj = __shfl_xor_sync(0xffffffffu, wj, off);
                if (ov > v || (ov == v && oj < wj)) { v = ov; wj = oj; }
            }
            if (l == 0) { best[b][i] = v; bp[b][i] = wj; }
            __syncwarp();
        }
    }
    __syncthreads();
    if (t == 0 || t == 32) {
        int b = t >> 5;
        int cur = lengths[b] - 1;
        float acc = 0.f;
        while (true) {
            bm[b * SEQ + cur] = 1.f;
            if (cur == 0) break;
            int prev = bp[b][cur];
            int start = cur > WSEG ? cur - WSEG : 0;
            acc += bs[(b * SEQ + cur) * WSEG + (prev - start)];
            cur = prev;
        }
        out[SB*SEQ*NCLS + SB*SEQ*2 + SB*SEQ + b] = acc;
    }
}

// ---------------- launch ----------------
extern "C" void kernel_launch(void* const* d_in, const int* in_sizes, int n_in,
                              void* d_out, int out_size)
{
    const float* x      = (const float*)d_in[0];
    const int*   lens   = (const int*)  d_in[1];
    const float* wih0f  = (const float*)d_in[2];
    const float* whh0f  = (const float*)d_in[3];
    const float* b0f    = (const float*)d_in[4];
    const float* wih0b  = (const float*)d_in[5];
    const float* whh0b  = (const float*)d_in[6];
    const float* b0b    = (const float*)d_in[7];
    const float* wih1f  = (const float*)d_in[8];
    const float* whh1f  = (const float*)d_in[9];
    const float* b1f    = (const float*)d_in[10];
    const float* wih1b  = (const float*)d_in[11];
    const float* whh1b  = (const float*)d_in[12];
    const float* b1b    = (const float*)d_in[13];
    const float* a_s0   = (const float*)d_in[14];
    const float* w_s1   = (const float*)d_in[15];
    const float* b_s1   = (const float*)d_in[16];
    const float* a_s1   = (const float*)d_in[17];
    const float* w_s2   = (const float*)d_in[18];
    const float* b_s2   = (const float*)d_in[19];
    const float* a_c0   = (const float*)d_in[20];
    const float* w_c1   = (const float*)d_in[21];
    const float* b_c1   = (const float*)d_in[22];
    const float* a_c1   = (const float*)d_in[23];
    const float* w_c2   = (const float*)d_in[24];
    const float* b_c2   = (const float*)d_in[25];
    const float* a_b0   = (const float*)d_in[26];
    const float* w_b1   = (const float*)d_in[27];
    const float* b_b1   = (const float*)d_in[28];
    const float* a_b1   = (const float*)d_in[29];
    const float* w_b2   = (const float*)d_in[30];
    const float* b_b2   = (const float*)d_in[31];
    float* out = (float*)d_out;

    cudaFuncSetAttribute(band_kernel, cudaFuncAttributeMaxDynamicSharedMemorySize, 183040);
    cudaFuncSetAttribute(dp_kernel,   cudaFuncAttributeMaxDynamicSharedMemorySize, 131072);

    proj_kernel<<<dim3(128, 2), 512>>>(x, IND, 0, wih0f, b0f, wih0b, b0b);
    lstm_kernel<<<16, 256>>>(whh0f, whh0b, 0);
    proj_kernel<<<dim3(128, 2), 512>>>(x, F2D, 1, wih1f, b1f, wih1b, b1b);
    lstm_kernel<<<16, 256>>>(whh1f, whh1b, 1);
    cumsum_kernel<<<2, 256>>>();
    pdpe_kernel<<<512, 128>>>(w_s1, b_s1, a_s0);
    clsbin_kernel<<<512, 160>>>(a_c0, w_c1, b_c1, a_c1, w_c2, b_c2,
                                a_b0, w_b1, b_b1, a_b1, w_b2, b_b2, out);
    band_kernel<<<510, 256, 183040>>>(w_s1, w_s2, b_s2, a_s0, a_s1);
    dp_kernel<<<1, 256, 131072>>>(lens, out);
}